// round 14
// baseline (speedup 1.0000x reference)
#include <cuda_runtime.h>
#include <cuda_fp16.h>
#include <cstdint>
#include <cstddef>

#define B_   8
#define T_   1024
#define C_   768
#define H_   12
#define D_   64
#define M_   (B_ * T_)     /* 8192 */
#define N1_  (3 * C_)      /* 2304 */

// ---------------- device-global scratch (all fp16 single) -------------------
__device__ __half g_a [(size_t)M_ * C_];     // hidden
__device__ __half g_c [(size_t)M_ * C_];     // ctx
__device__ __half g_wq[(size_t)N1_ * C_];    // qkv_w^T [2304,768]
__device__ __half g_wp[(size_t)C_ * C_];     // proj_w^T [768,768]
__device__ __half g_q [(size_t)M_ * C_];     // [B*H,T,D], pre-scaled 0.125
__device__ __half g_k [(size_t)M_ * C_];
__device__ __half g_v [(size_t)M_ * C_];

// ---------------- PTX helpers ----------------------------------------------
__device__ __forceinline__ uint32_t smem_u32(const void* p) {
    uint32_t a;
    asm("{ .reg .u64 t; cvta.to.shared.u64 t, %1; cvt.u32.u64 %0, t; }"
        : "=r"(a) : "l"(p));
    return a;
}

#define CP_ASYNC16(dst, src) \
    asm volatile("cp.async.cg.shared.global [%0], [%1], 16;" \
                 :: "r"(dst), "l"(src) : "memory")
#define CP_COMMIT() asm volatile("cp.async.commit_group;" ::: "memory")
#define CP_WAIT(n)  asm volatile("cp.async.wait_group %0;" :: "n"(n) : "memory")

__device__ __forceinline__ void ldsm4(uint32_t* r, uint32_t a) {
    asm volatile("ldmatrix.sync.aligned.m8n8.x4.shared.b16 {%0,%1,%2,%3}, [%4];"
                 : "=r"(r[0]), "=r"(r[1]), "=r"(r[2]), "=r"(r[3]) : "r"(a));
}
__device__ __forceinline__ void ldsm4t(uint32_t* r, uint32_t a) {
    asm volatile("ldmatrix.sync.aligned.m8n8.x4.trans.shared.b16 {%0,%1,%2,%3}, [%4];"
                 : "=r"(r[0]), "=r"(r[1]), "=r"(r[2]), "=r"(r[3]) : "r"(a));
}

__device__ __forceinline__ void mma_f16(float* c, const uint32_t* a,
                                        uint32_t b0, uint32_t b1) {
    asm volatile(
        "mma.sync.aligned.m16n8k16.row.col.f32.f16.f16.f32 "
        "{%0,%1,%2,%3}, {%4,%5,%6,%7}, {%8,%9}, {%0,%1,%2,%3};"
        : "+f"(c[0]), "+f"(c[1]), "+f"(c[2]), "+f"(c[3])
        : "r"(a[0]), "r"(a[1]), "r"(a[2]), "r"(a[3]), "r"(b0), "r"(b1));
}

__device__ __forceinline__ uint32_t pack_h2(float x, float y) {
    __half2 h = __halves2half2(__float2half_rn(x), __float2half_rn(y));
    return *(uint32_t*)&h;
}

// ---------------- fused conversion kernel -----------------------------------
// blocks [0, NB_H): hidden fp32 -> g_a fp16 (elementwise)
// blocks [NB_H, NB_H+NB_WQ): qkv_w transpose -> g_wq
// blocks [NB_H+NB_WQ, ...): proj_w transpose -> g_wp
#define NB_H  ((M_ * C_) / 256)          /* 24576 */
#define NB_WQ ((N1_ / 32) * (C_ / 32))   /* 1728 */
#define NB_WP ((C_ / 32) * (C_ / 32))    /* 576 */

__global__ void conv_all_kernel(const float* __restrict__ hidden,
                                const float* __restrict__ qkv_w,
                                const float* __restrict__ proj_w)
{
    const int bid = blockIdx.x;
    const int tid = threadIdx.x;

    if (bid < NB_H) {
        int i = bid * 256 + tid;
        g_a[i] = __float2half_rn(hidden[i]);
        return;
    }

    // transpose part: W [K, N] fp32 -> W^T [N, K] fp16
    __shared__ float tile[32][33];
    const float* src;
    __half* dst;
    int N, b;
    if (bid < NB_H + NB_WQ) {
        b = bid - NB_H;  src = qkv_w;  dst = g_wq;  N = N1_;
    } else {
        b = bid - NB_H - NB_WQ;  src = proj_w;  dst = g_wp;  N = C_;
    }
    const int nblk = N / 32;
    const int nx = (b % nblk) * 32;
    const int kx = (b / nblk) * 32;
    const int tx = tid & 31;
    const int ty = tid >> 5;           // 0..7
    for (int i = ty; i < 32; i += 8)
        tile[i][tx] = src[(size_t)(kx + i) * N + nx + tx];
    __syncthreads();
    for (int i = ty; i < 32; i += 8)
        dst[(size_t)(nx + i) * C_ + kx + tx] = __float2half_rn(tile[tx][i]);
}

// ---------------- mma.sync fp16 GEMM ----------------------------------------
// MODE 0: QKV. CTA 128x128, warp 32x64 (4x2 warps). grid 18x64.
// MODE 1: proj. CTA 128x64, warp 32x32 (4x2 warps). grid 12x64 (2.6 waves).
#define BKE 32
#define KSB 80
#define TILE_A (128 * KSB)           /* 10240 */
#define NSTG 3
#define NKT 24

template <int MODE>
__global__ __launch_bounds__(256, 2)
void gemm_mma_kernel(const float* __restrict__ bias, float* __restrict__ out)
{
    constexpr int BN  = MODE ? 64 : 128;
    constexpr int WN  = BN / 2;                 // warp n-width (32 | 64)
    constexpr int NTW = WN / 8;                 // n-tiles per warp (4 | 8)
    constexpr int NP  = NTW / 2;                // b-ldsm4 per kk (2 | 4)
    constexpr uint32_t TILE_B_SZ = (uint32_t)BN * KSB;
    constexpr uint32_t STG_B = TILE_A + TILE_B_SZ;
    constexpr int NCHUNK = (128 + BN) * 4;      // 16B chunks per stage

    extern __shared__ char smem[];
    const uint32_t sbase = smem_u32(smem);
    const int tid = threadIdx.x;
    const int wid = tid >> 5;          // 0..7
    const int l   = tid & 31;
    const int gm0 = blockIdx.y * 128;
    const int gn0 = blockIdx.x * BN;

    const __half* gA = MODE ? g_c  : g_a;
    const __half* gB = MODE ? g_wp : g_wq;

    const int m0 = (wid & 3) * 32;
    const int n0 = (wid >> 2) * WN;

    const int lq = l >> 3, lr = l & 7;
    const uint32_t a_off = (uint32_t)((m0 + (lq & 1) * 8 + lr) * KSB + ((lq >> 1) * 8) * 2);
    const uint32_t b_off = (uint32_t)((n0 + (lq >> 1) * 8 + lr) * KSB + ((lq & 1) * 8) * 2);

    float acc[2][NTW][4];
#pragma unroll
    for (int mt = 0; mt < 2; mt++)
#pragma unroll
        for (int nt = 0; nt < NTW; nt++)
#pragma unroll
            for (int j = 0; j < 4; j++) acc[mt][nt][j] = 0.f;

    auto issue_stage = [&](int kt, int s) {
        const int k0 = kt * BKE;
        const uint32_t sb = sbase + (uint32_t)s * STG_B;
#pragma unroll
        for (int c = tid; c < NCHUNK; c += 256) {
            const int row = c >> 2, ch = c & 3;
            const __half* src = (row < 128) ? gA : gB;
            const int grow = (row < 128) ? (gm0 + row) : (gn0 + row - 128);
            CP_ASYNC16(sb + (uint32_t)row * KSB + ch * 16,
                       src + (size_t)grow * C_ + k0 + ch * 8);
        }
    };

    issue_stage(0, 0); CP_COMMIT();
    issue_stage(1, 1); CP_COMMIT();

#pragma unroll 1
    for (int kt = 0; kt < NKT; kt++) {
        const int s = kt % NSTG;
        if (kt + 1 < NKT) { CP_WAIT(1); } else { CP_WAIT(0); }
        __syncthreads();
        if (kt + 2 < NKT) {
            issue_stage(kt + 2, (kt + 2) % NSTG);
            CP_COMMIT();
        }

        const uint32_t aP = sbase + (uint32_t)s * STG_B + a_off;
        const uint32_t bP = sbase + (uint32_t)s * STG_B + TILE_A + b_off;

#pragma unroll
        for (int kk = 0; kk < 2; kk++) {
            const uint32_t ko = kk * 32;
            uint32_t ar[2][4], br[NP][4];
#pragma unroll
            for (int mt = 0; mt < 2; mt++)
                ldsm4(ar[mt], aP + mt * (16 * KSB) + ko);
#pragma unroll
            for (int p = 0; p < NP; p++)
                ldsm4(br[p], bP + p * (16 * KSB) + ko);
#pragma unroll
            for (int mt = 0; mt < 2; mt++)
#pragma unroll
                for (int nt = 0; nt < NTW; nt++) {
                    const int p = nt >> 1, o = (nt & 1) * 2;
                    mma_f16(acc[mt][nt], ar[mt], br[p][o], br[p][o + 1]);
                }
        }
    }

    // ---------------- epilogue ----------------------------------------------
    const int gr_base = gm0 + m0 + (l >> 2);
    const int gc_loc  = 2 * (l & 3);

    if (MODE == 0) {
        const int which    = gn0 / C_;          // 128 | 768 boundaries align
        const int rem_base = gn0 - which * C_;
        __half* dst = (which == 0) ? g_q : (which == 1) ? g_k : g_v;
        const float sc = (which == 0) ? 0.125f : 1.0f;
#pragma unroll
        for (int mt = 0; mt < 2; mt++)
#pragma unroll
            for (int nt = 0; nt < NTW; nt++) {
                const float* c = acc[mt][nt];
                const int gcn = n0 + nt * 8 + gc_loc;
                const int gc  = gn0 + gcn;
                float2 bb = *(const float2*)&bias[gc];
                const int rem = rem_base + gcn;
                const int h = rem >> 6, d = rem & 63;
#pragma unroll
                for (int hf = 0; hf < 2; hf++) {
                    const int gr = gr_base + mt * 16 + hf * 8;
                    const int b  = gr >> 10, tq = gr & 1023;
                    size_t idx = (((size_t)(b * H_ + h)) * T_ + tq) * D_ + d;
                    *(uint32_t*)&dst[idx] = pack_h2((c[hf * 2 + 0] + bb.x) * sc,
                                                    (c[hf * 2 + 1] + bb.y) * sc);
                }
            }
    } else {
#pragma unroll
        for (int mt = 0; mt < 2; mt++)
#pragma unroll
            for (int nt = 0; nt < NTW; nt++) {
                const float* c = acc[mt][nt];
                const int gc = gn0 + n0 + nt * 8 + gc_loc;
                float2 bb = *(const float2*)&bias[gc];
#pragma unroll
                for (int hf = 0; hf < 2; hf++) {
                    const int gr = gr_base + mt * 16 + hf * 8;
                    float2 o;
                    o.x = c[hf * 2 + 0] + bb.x;
                    o.y = c[hf * 2 + 1] + bb.y;
                    *(float2*)&out[(size_t)gr * C_ + gc] = o;
                }
            }
    }
}

#define GEMM_SMEM0 (NSTG * (TILE_A + 128 * KSB))  /* 61440 */
#define GEMM_SMEM1 (NSTG * (TILE_A + 64 * KSB))   /* 46080 */

// ---------------- tensor-core flash attention (fp16, register P) ------------
// CTA: 128 q-rows x (b,h). 8 warps x 16 rows. 64-key tiles, 16 iters.
// 3-stage KV ring, ONE barrier per iteration; P stays in registers.
#define NT_  16
#define ROWB 144
#define SQ    0                               /* 18432 */
#define SK(s) (18432 + (s) * 18432)           /* K tile (9216) */
#define SV(s) (18432 + (s) * 18432 + 9216)    /* V tile (9216) */
#define ATTN_SMEM (18432 * 4)                 /* 73728 */

__global__ __launch_bounds__(256, 2) void attn_mma_kernel()
{
    extern __shared__ char smem[];
    const uint32_t sbase = smem_u32(smem);
    const int tid = threadIdx.x, wid = tid >> 5, l = tid & 31;
    const int bh = blockIdx.y, q0 = blockIdx.x * 128;
    const size_t hb = (size_t)bh * T_ * D_;
    const __half *Qg = g_q + hb, *Kg = g_k + hb, *Vg = g_v + hb;

    const int m0 = wid * 16;
    const int lq = l >> 3, lr = l & 7;
    const uint32_t a_off = (uint32_t)((m0 + (lq & 1) * 8 + lr) * ROWB + (lq >> 1) * 16);
    const uint32_t b_off = (uint32_t)(((lq >> 1) * 8 + lr) * ROWB + (lq & 1) * 16);
    const uint32_t v_off = (uint32_t)(((lq & 1) * 8 + lr) * ROWB + (lq >> 1) * 16);

    auto load_kv = [&](int kt, int s) {
        const int r0 = kt * 64;
#pragma unroll
        for (int a = 0; a < 2; a++) {
            const __half* src = a ? Vg : Kg;
            const uint32_t dst = sbase + (a ? SV(s) : SK(s));
#pragma unroll
            for (int it = 0; it < 2; it++) {
                int c = it * 256 + tid;
                int row = c >> 3, ch = c & 7;
                CP_ASYNC16(dst + row * ROWB + ch * 16,
                           src + (size_t)(r0 + row) * D_ + ch * 8);
            }
        }
    };

    // prologue: Q + kv0 in one group, kv1 in a second
#pragma unroll
    for (int it = 0; it < 4; it++) {
        int c = it * 256 + tid;
        int row = c >> 3, ch = c & 7;
        CP_ASYNC16(sbase + SQ + row * ROWB + ch * 16,
                   Qg + (size_t)(q0 + row) * D_ + ch * 8);
    }
    load_kv(0, 0); CP_COMMIT();
    load_kv(1, 1); CP_COMMIT();

    uint32_t qf[4][4];
    float mrow[2] = {-1e30f, -1e30f}, lsum[2] = {0.f, 0.f};
    float acc[8][4];
#pragma unroll
    for (int nt = 0; nt < 8; nt++)
#pragma unroll
        for (int j = 0; j < 4; j++) acc[nt][j] = 0.f;

#pragma unroll 1
    for (int kt = 0; kt < NT_; kt++) {
        const int s = kt % 3;
        if (kt + 1 < NT_) { CP_WAIT(1); } else { CP_WAIT(0); }
        __syncthreads();
        if (kt == 0) {
#pragma unroll
            for (int kk = 0; kk < 4; kk++)
                ldsm4(qf[kk], sbase + SQ + a_off + kk * 32);
        }
        if (kt + 2 < NT_) {
            load_kv(kt + 2, (kt + 2) % 3);
            CP_COMMIT();
        }

        // ---- S = Q K^T ----
        float sc[8][4];
#pragma unroll
        for (int nt = 0; nt < 8; nt++)
#pragma unroll
            for (int j = 0; j < 4; j++) sc[nt][j] = 0.f;

        const uint32_t kb = sbase + SK(s) + b_off;
#pragma unroll
        for (int kk = 0; kk < 4; kk++) {
            uint32_t b4[4][4];
#pragma unroll
            for (int p = 0; p < 4; p++)
                ldsm4(b4[p], kb + p * (16 * ROWB) + kk * 32);
#pragma unroll
            for (int nt = 0; nt < 8; nt++) {
                const int p = nt >> 1, o = (nt & 1) * 2;
                mma_f16(sc[nt], qf[kk], b4[p][o], b4[p][o + 1]);
            }
        }

        // ---- online softmax (p kept in sc registers) ----
        float mx0 = sc[0][0], mx1 = sc[0][2];
#pragma unroll
        for (int nt = 0; nt < 8; nt++) {
            mx0 = fmaxf(mx0, fmaxf(sc[nt][0], sc[nt][1]));
            mx1 = fmaxf(mx1, fmaxf(sc[nt][2], sc[nt][3]));
        }
        mx0 = fmaxf(mx0, __shfl_xor_sync(0xffffffffu, mx0, 1));
        mx0 = fmaxf(mx0, __shfl_xor_sync(0xffffffffu, mx0, 2));
        mx1 = fmaxf(mx1, __shfl_xor_sync(0xffffffffu, mx1, 1));
        mx1 = fmaxf(mx1, __shfl_xor_sync(0xffffffffu, mx1, 2));
        const float mn0 = fmaxf(mrow[0], mx0);
        const float mn1 = fmaxf(mrow[1], mx1);
        const float f0 = __expf(mrow[0] - mn0);
        const float f1 = __expf(mrow[1] - mn1);
        mrow[0] = mn0; mrow[1] = mn1;

        float rs0 = 0.f, rs1 = 0.f;
#pragma unroll
        for (int nt = 0; nt < 8; nt++) {
            float p0 = __expf(sc[nt][0] - mn0);
            float p1 = __expf(sc[nt][1] - mn0);
            float p2 = __expf(sc[nt][2] - mn1);
            float p3 = __expf(sc[nt][3] - mn1);
            rs0 += p0 + p1; rs1 += p2 + p3;
            sc[nt][0] = p0; sc[nt][1] = p1; sc[nt][2] = p2; sc[nt][3] = p3;
            acc[nt][0] *= f0; acc[nt][1] *= f0;
            acc[nt][2] *= f1; acc[nt][3] *= f1;
        }
        rs0 += __shfl_xor_sync(0xffffffffu, rs0, 1);
        rs0 += __shfl_xor_sync(0xffffffffu, rs0, 2);
        rs1 += __shfl_xor_sync(0xffffffffu, rs1, 1);
        rs1 += __shfl_xor_sync(0xffffffffu, rs1, 2);
        lsum[0] = lsum[0] * f0 + rs0;
        lsum[1] = lsum[1] * f1 + rs1;

        // ---- O += P V, P fragments built in registers ----
        const uint32_t vb = sbase + SV(s) + v_off;
#pragma unroll
        for (int kk = 0; kk < 4; kk++) {
            uint32_t pf[4];
            pf[0] = pack_h2(sc[2 * kk][0],     sc[2 * kk][1]);
            pf[1] = pack_h2(sc[2 * kk][2],     sc[2 * kk][3]);
            pf[2] = pack_h2(sc[2 * kk + 1][0], sc[2 * kk + 1][1]);
            pf[3] = pack_h2(sc[2 * kk + 1][2], sc[2 * kk + 1][3]);
            uint32_t v4[4][4];
#pragma unroll
            for (int p = 0; p < 4; p++)
                ldsm4t(v4[p], vb + kk * (16 * ROWB) + p * 32);
#pragma unroll
            for (int nt = 0; nt < 8; nt++) {
                const int p = nt >> 1, o = (nt & 1) * 2;
                mma_f16(acc[nt], pf, v4[p][o], v4[p][o + 1]);
            }
        }
    }

    // ---- epilogue: ctx -> fp16 [B*T, C] ----
    const int b = bh / H_, h = bh - b * H_;
    const float i0 = 1.f / lsum[0];
    const float i1 = 1.f / lsum[1];
    const int r0 = q0 + m0 + (l >> 2);
    const size_t base0 = ((size_t)b * T_ + r0) * C_ + h * D_ + 2 * (l & 3);
    const size_t base1 = base0 + 8 * (size_t)C_;
#pragma unroll
    for (int nt = 0; nt < 8; nt++) {
        *(uint32_t*)&g_c[base0 + nt * 8] = pack_h2(acc[nt][0] * i0, acc[nt][1] * i0);
        *(uint32_t*)&g_c[base1 + nt * 8] = pack_h2(acc[nt][2] * i1, acc[nt][3] * i1);
    }
}

// ---------------------------------------------------------------------------
extern "C" void kernel_launch(void* const* d_in, const int* in_sizes, int n_in,
                              void* d_out, int out_size)
{
    const float* hidden = (const float*)d_in[0];
    const float* qkv_w  = (const float*)d_in[1];
    const float* qkv_b  = (const float*)d_in[2];
    const float* proj_w = (const float*)d_in[3];
    const float* proj_b = (const float*)d_in[4];
    float* out = (float*)d_out;
    (void)in_sizes; (void)n_in; (void)out_size;

    cudaFuncSetAttribute(gemm_mma_kernel<0>,
                         cudaFuncAttributeMaxDynamicSharedMemorySize, GEMM_SMEM0);
    cudaFuncSetAttribute(gemm_mma_kernel<1>,
                         cudaFuncAttributeMaxDynamicSharedMemorySize, GEMM_SMEM1);
    cudaFuncSetAttribute(attn_mma_kernel,
                         cudaFuncAttributeMaxDynamicSharedMemorySize, ATTN_SMEM);

    // 0) fused operand conversions (one launch)
    conv_all_kernel<<<NB_H + NB_WQ + NB_WP, 256>>>(hidden, qkv_w, proj_w);

    // 1) QKV projection -> Q (pre-scaled) / K / V fp16
    gemm_mma_kernel<0><<<dim3(N1_ / 128, M_ / 128), 256, GEMM_SMEM0>>>(qkv_b, nullptr);

    // 2) attention -> ctx fp16
    attn_mma_kernel<<<dim3(T_ / 128, B_ * H_), 256, ATTN_SMEM>>>();

    // 3) output projection (128x64 CTAs, 2.6 waves) -> out fp32
    gemm_mma_kernel<1><<<dim3(C_ / 64, M_ / 128), 256, GEMM_SMEM1>>>(proj_b, out);
}

// round 15
// speedup vs baseline: 1.0392x; 1.0392x over previous
#include <cuda_runtime.h>
#include <cuda_fp16.h>
#include <cstdint>
#include <cstddef>

#define B_   8
#define T_   1024
#define C_   768
#define H_   12
#define D_   64
#define M_   (B_ * T_)     /* 8192 */
#define N1_  (3 * C_)      /* 2304 */

// ---------------- device-global scratch (all fp16 single) -------------------
__device__ __half g_a [(size_t)M_ * C_];     // hidden
__device__ __half g_c [(size_t)M_ * C_];     // ctx
__device__ __half g_wq[(size_t)N1_ * C_];    // qkv_w^T [2304,768]
__device__ __half g_wp[(size_t)C_ * C_];     // proj_w^T [768,768]
__device__ __half g_q [(size_t)M_ * C_];     // [B*H,T,D], pre-scaled 0.125
__device__ __half g_k [(size_t)M_ * C_];
__device__ __half g_v [(size_t)M_ * C_];

// ---------------- PTX helpers ----------------------------------------------
__device__ __forceinline__ uint32_t smem_u32(const void* p) {
    uint32_t a;
    asm("{ .reg .u64 t; cvta.to.shared.u64 t, %1; cvt.u32.u64 %0, t; }"
        : "=r"(a) : "l"(p));
    return a;
}

#define CP_ASYNC16(dst, src) \
    asm volatile("cp.async.cg.shared.global [%0], [%1], 16;" \
                 :: "r"(dst), "l"(src) : "memory")
#define CP_COMMIT() asm volatile("cp.async.commit_group;" ::: "memory")
#define CP_WAIT(n)  asm volatile("cp.async.wait_group %0;" :: "n"(n) : "memory")

__device__ __forceinline__ void ldsm4(uint32_t* r, uint32_t a) {
    asm volatile("ldmatrix.sync.aligned.m8n8.x4.shared.b16 {%0,%1,%2,%3}, [%4];"
                 : "=r"(r[0]), "=r"(r[1]), "=r"(r[2]), "=r"(r[3]) : "r"(a));
}
__device__ __forceinline__ void ldsm4t(uint32_t* r, uint32_t a) {
    asm volatile("ldmatrix.sync.aligned.m8n8.x4.trans.shared.b16 {%0,%1,%2,%3}, [%4];"
                 : "=r"(r[0]), "=r"(r[1]), "=r"(r[2]), "=r"(r[3]) : "r"(a));
}

__device__ __forceinline__ void mma_f16(float* c, const uint32_t* a,
                                        uint32_t b0, uint32_t b1) {
    asm volatile(
        "mma.sync.aligned.m16n8k16.row.col.f32.f16.f16.f32 "
        "{%0,%1,%2,%3}, {%4,%5,%6,%7}, {%8,%9}, {%0,%1,%2,%3};"
        : "+f"(c[0]), "+f"(c[1]), "+f"(c[2]), "+f"(c[3])
        : "r"(a[0]), "r"(a[1]), "r"(a[2]), "r"(a[3]), "r"(b0), "r"(b1));
}

__device__ __forceinline__ uint32_t pack_h2(float x, float y) {
    __half2 h = __halves2half2(__float2half_rn(x), __float2half_rn(y));
    return *(uint32_t*)&h;
}

// ---------------- fused conversion kernel -----------------------------------
#define NB_H  ((M_ * C_) / 256)          /* 24576 */
#define NB_WQ ((N1_ / 32) * (C_ / 32))   /* 1728 */
#define NB_WP ((C_ / 32) * (C_ / 32))    /* 576 */

__global__ void conv_all_kernel(const float* __restrict__ hidden,
                                const float* __restrict__ qkv_w,
                                const float* __restrict__ proj_w)
{
    const int bid = blockIdx.x;
    const int tid = threadIdx.x;

    if (bid < NB_H) {
        int i = bid * 256 + tid;
        g_a[i] = __float2half_rn(hidden[i]);
        return;
    }

    __shared__ float tile[32][33];
    const float* src;
    __half* dst;
    int N, b;
    if (bid < NB_H + NB_WQ) {
        b = bid - NB_H;  src = qkv_w;  dst = g_wq;  N = N1_;
    } else {
        b = bid - NB_H - NB_WQ;  src = proj_w;  dst = g_wp;  N = C_;
    }
    const int nblk = N / 32;
    const int nx = (b % nblk) * 32;
    const int kx = (b / nblk) * 32;
    const int tx = tid & 31;
    const int ty = tid >> 5;
    for (int i = ty; i < 32; i += 8)
        tile[i][tx] = src[(size_t)(kx + i) * N + nx + tx];
    __syncthreads();
    for (int i = ty; i < 32; i += 8)
        dst[(size_t)(nx + i) * C_ + kx + tx] = __float2half_rn(tile[tx][i]);
}

// ---------------- mma.sync fp16 GEMM ----------------------------------------
// Both modes: CTA 128x128, 256 thr, 8 warps 4x2, warp 32x64, 3-stage,
// 2 CTAs/SM (barrier drains in one CTA hidden by the other).
#define BKE 32
#define KSB 80
#define TILE_A (128 * KSB)           /* 10240 */
#define NSTG 3
#define NKT 24
#define STG_B (2 * TILE_A)
#define GEMM_SMEM (NSTG * STG_B)     /* 61440 */

template <int MODE>
__global__ __launch_bounds__(256, 2)
void gemm_mma_kernel(const float* __restrict__ bias, float* __restrict__ out)
{
    extern __shared__ char smem[];
    const uint32_t sbase = smem_u32(smem);
    const int tid = threadIdx.x;
    const int wid = tid >> 5;          // 0..7
    const int l   = tid & 31;
    const int gm0 = blockIdx.y * 128;
    const int gn0 = blockIdx.x * 128;

    const __half* gA = MODE ? g_c  : g_a;
    const __half* gB = MODE ? g_wp : g_wq;

    const int m0 = (wid & 3) * 32;
    const int n0 = (wid >> 2) * 64;

    const int lq = l >> 3, lr = l & 7;
    const uint32_t a_off = (uint32_t)((m0 + (lq & 1) * 8 + lr) * KSB + ((lq >> 1) * 8) * 2);
    const uint32_t b_off = (uint32_t)((n0 + (lq >> 1) * 8 + lr) * KSB + ((lq & 1) * 8) * 2);

    float acc[2][8][4];
#pragma unroll
    for (int mt = 0; mt < 2; mt++)
#pragma unroll
        for (int nt = 0; nt < 8; nt++)
#pragma unroll
            for (int j = 0; j < 4; j++) acc[mt][nt][j] = 0.f;

    auto issue_stage = [&](int kt, int s) {
        const int k0 = kt * BKE;
        const uint32_t sb = sbase + (uint32_t)s * STG_B;
#pragma unroll
        for (int i = 0; i < 4; i++) {
            const int c = i * 256 + tid;          // 0..1023
            const int row = c >> 2, ch = c & 3;
            const __half* src = (row < 128) ? gA : gB;
            const int grow = (row < 128) ? (gm0 + row) : (gn0 + row - 128);
            CP_ASYNC16(sb + (uint32_t)row * KSB + ch * 16,
                       src + (size_t)grow * C_ + k0 + ch * 8);
        }
    };

    issue_stage(0, 0); CP_COMMIT();
    issue_stage(1, 1); CP_COMMIT();

#pragma unroll 1
    for (int kt = 0; kt < NKT; kt++) {
        const int s = kt % NSTG;
        if (kt + 1 < NKT) { CP_WAIT(1); } else { CP_WAIT(0); }
        __syncthreads();
        if (kt + 2 < NKT) {
            issue_stage(kt + 2, (kt + 2) % NSTG);
            CP_COMMIT();
        }

        const uint32_t aP = sbase + (uint32_t)s * STG_B + a_off;
        const uint32_t bP = sbase + (uint32_t)s * STG_B + TILE_A + b_off;

#pragma unroll
        for (int kk = 0; kk < 2; kk++) {
            const uint32_t ko = kk * 32;
            uint32_t ar[2][4], br[4][4];
#pragma unroll
            for (int mt = 0; mt < 2; mt++)
                ldsm4(ar[mt], aP + mt * (16 * KSB) + ko);
#pragma unroll
            for (int p = 0; p < 4; p++)
                ldsm4(br[p], bP + p * (16 * KSB) + ko);
#pragma unroll
            for (int mt = 0; mt < 2; mt++)
#pragma unroll
                for (int nt = 0; nt < 8; nt++) {
                    const int p = nt >> 1, o = (nt & 1) * 2;
                    mma_f16(acc[mt][nt], ar[mt], br[p][o], br[p][o + 1]);
                }
        }
    }

    // ---------------- epilogue ----------------------------------------------
    const int gr_base = gm0 + m0 + (l >> 2);
    const int gc_loc  = 2 * (l & 3);

    if (MODE == 0) {
        const int which    = gn0 / C_;
        const int rem_base = gn0 - which * C_;
        __half* dst = (which == 0) ? g_q : (which == 1) ? g_k : g_v;
        const float sc = (which == 0) ? 0.125f : 1.0f;
#pragma unroll
        for (int mt = 0; mt < 2; mt++)
#pragma unroll
            for (int nt = 0; nt < 8; nt++) {
                const float* c = acc[mt][nt];
                const int gcn = n0 + nt * 8 + gc_loc;
                const int gc  = gn0 + gcn;
                float2 bb = *(const float2*)&bias[gc];
                const int rem = rem_base + gcn;
                const int h = rem >> 6, d = rem & 63;
#pragma unroll
                for (int hf = 0; hf < 2; hf++) {
                    const int gr = gr_base + mt * 16 + hf * 8;
                    const int b  = gr >> 10, tq = gr & 1023;
                    size_t idx = (((size_t)(b * H_ + h)) * T_ + tq) * D_ + d;
                    *(uint32_t*)&dst[idx] = pack_h2((c[hf * 2 + 0] + bb.x) * sc,
                                                    (c[hf * 2 + 1] + bb.y) * sc);
                }
            }
    } else {
#pragma unroll
        for (int mt = 0; mt < 2; mt++)
#pragma unroll
            for (int nt = 0; nt < 8; nt++) {
                const float* c = acc[mt][nt];
                const int gc = gn0 + n0 + nt * 8 + gc_loc;
                float2 bb = *(const float2*)&bias[gc];
#pragma unroll
                for (int hf = 0; hf < 2; hf++) {
                    const int gr = gr_base + mt * 16 + hf * 8;
                    float2 o;
                    o.x = c[hf * 2 + 0] + bb.x;
                    o.y = c[hf * 2 + 1] + bb.y;
                    *(float2*)&out[(size_t)gr * C_ + gc] = o;
                }
            }
    }
}

// ---------------- tensor-core flash attention (fp16, register P) ------------
// CTA: 128 q-rows x (b,h). 8 warps x 16 rows. 64-key tiles, 16 iters.
// 3-stage KV ring, ONE barrier per iteration; P stays in registers.
#define NT_  16
#define ROWB 144
#define SQ    0                               /* 18432 */
#define SK(s) (18432 + (s) * 18432)           /* K tile (9216) */
#define SV(s) (18432 + (s) * 18432 + 9216)    /* V tile (9216) */
#define ATTN_SMEM (18432 * 4)                 /* 73728 */

__global__ __launch_bounds__(256, 2) void attn_mma_kernel()
{
    extern __shared__ char smem[];
    const uint32_t sbase = smem_u32(smem);
    const int tid = threadIdx.x, wid = tid >> 5, l = tid & 31;
    const int bh = blockIdx.y, q0 = blockIdx.x * 128;
    const size_t hb = (size_t)bh * T_ * D_;
    const __half *Qg = g_q + hb, *Kg = g_k + hb, *Vg = g_v + hb;

    const int m0 = wid * 16;
    const int lq = l >> 3, lr = l & 7;
    const uint32_t a_off = (uint32_t)((m0 + (lq & 1) * 8 + lr) * ROWB + (lq >> 1) * 16);
    const uint32_t b_off = (uint32_t)(((lq >> 1) * 8 + lr) * ROWB + (lq & 1) * 16);
    const uint32_t v_off = (uint32_t)(((lq & 1) * 8 + lr) * ROWB + (lq >> 1) * 16);

    auto load_kv = [&](int kt, int s) {
        const int r0 = kt * 64;
#pragma unroll
        for (int a = 0; a < 2; a++) {
            const __half* src = a ? Vg : Kg;
            const uint32_t dst = sbase + (a ? SV(s) : SK(s));
#pragma unroll
            for (int it = 0; it < 2; it++) {
                int c = it * 256 + tid;
                int row = c >> 3, ch = c & 7;
                CP_ASYNC16(dst + row * ROWB + ch * 16,
                           src + (size_t)(r0 + row) * D_ + ch * 8);
            }
        }
    };

#pragma unroll
    for (int it = 0; it < 4; it++) {
        int c = it * 256 + tid;
        int row = c >> 3, ch = c & 7;
        CP_ASYNC16(sbase + SQ + row * ROWB + ch * 16,
                   Qg + (size_t)(q0 + row) * D_ + ch * 8);
    }
    load_kv(0, 0); CP_COMMIT();
    load_kv(1, 1); CP_COMMIT();

    uint32_t qf[4][4];
    float mrow[2] = {-1e30f, -1e30f}, lsum[2] = {0.f, 0.f};
    float acc[8][4];
#pragma unroll
    for (int nt = 0; nt < 8; nt++)
#pragma unroll
        for (int j = 0; j < 4; j++) acc[nt][j] = 0.f;

#pragma unroll 1
    for (int kt = 0; kt < NT_; kt++) {
        const int s = kt % 3;
        if (kt + 1 < NT_) { CP_WAIT(1); } else { CP_WAIT(0); }
        __syncthreads();
        if (kt == 0) {
#pragma unroll
            for (int kk = 0; kk < 4; kk++)
                ldsm4(qf[kk], sbase + SQ + a_off + kk * 32);
        }
        if (kt + 2 < NT_) {
            load_kv(kt + 2, (kt + 2) % 3);
            CP_COMMIT();
        }

        // ---- S = Q K^T ----
        float sc[8][4];
#pragma unroll
        for (int nt = 0; nt < 8; nt++)
#pragma unroll
            for (int j = 0; j < 4; j++) sc[nt][j] = 0.f;

        const uint32_t kb = sbase + SK(s) + b_off;
#pragma unroll
        for (int kk = 0; kk < 4; kk++) {
            uint32_t b4[4][4];
#pragma unroll
            for (int p = 0; p < 4; p++)
                ldsm4(b4[p], kb + p * (16 * ROWB) + kk * 32);
#pragma unroll
            for (int nt = 0; nt < 8; nt++) {
                const int p = nt >> 1, o = (nt & 1) * 2;
                mma_f16(sc[nt], qf[kk], b4[p][o], b4[p][o + 1]);
            }
        }

        // ---- online softmax (p kept in sc registers) ----
        float mx0 = sc[0][0], mx1 = sc[0][2];
#pragma unroll
        for (int nt = 0; nt < 8; nt++) {
            mx0 = fmaxf(mx0, fmaxf(sc[nt][0], sc[nt][1]));
            mx1 = fmaxf(mx1, fmaxf(sc[nt][2], sc[nt][3]));
        }
        mx0 = fmaxf(mx0, __shfl_xor_sync(0xffffffffu, mx0, 1));
        mx0 = fmaxf(mx0, __shfl_xor_sync(0xffffffffu, mx0, 2));
        mx1 = fmaxf(mx1, __shfl_xor_sync(0xffffffffu, mx1, 1));
        mx1 = fmaxf(mx1, __shfl_xor_sync(0xffffffffu, mx1, 2));
        const float mn0 = fmaxf(mrow[0], mx0);
        const float mn1 = fmaxf(mrow[1], mx1);
        const float f0 = __expf(mrow[0] - mn0);
        const float f1 = __expf(mrow[1] - mn1);
        mrow[0] = mn0; mrow[1] = mn1;

        float rs0 = 0.f, rs1 = 0.f;
#pragma unroll
        for (int nt = 0; nt < 8; nt++) {
            float p0 = __expf(sc[nt][0] - mn0);
            float p1 = __expf(sc[nt][1] - mn0);
            float p2 = __expf(sc[nt][2] - mn1);
            float p3 = __expf(sc[nt][3] - mn1);
            rs0 += p0 + p1; rs1 += p2 + p3;
            sc[nt][0] = p0; sc[nt][1] = p1; sc[nt][2] = p2; sc[nt][3] = p3;
            acc[nt][0] *= f0; acc[nt][1] *= f0;
            acc[nt][2] *= f1; acc[nt][3] *= f1;
        }
        rs0 += __shfl_xor_sync(0xffffffffu, rs0, 1);
        rs0 += __shfl_xor_sync(0xffffffffu, rs0, 2);
        rs1 += __shfl_xor_sync(0xffffffffu, rs1, 1);
        rs1 += __shfl_xor_sync(0xffffffffu, rs1, 2);
        lsum[0] = lsum[0] * f0 + rs0;
        lsum[1] = lsum[1] * f1 + rs1;

        // ---- O += P V, P fragments built in registers ----
        const uint32_t vb = sbase + SV(s) + v_off;
#pragma unroll
        for (int kk = 0; kk < 4; kk++) {
            uint32_t pf[4];
            pf[0] = pack_h2(sc[2 * kk][0],     sc[2 * kk][1]);
            pf[1] = pack_h2(sc[2 * kk][2],     sc[2 * kk][3]);
            pf[2] = pack_h2(sc[2 * kk + 1][0], sc[2 * kk + 1][1]);
            pf[3] = pack_h2(sc[2 * kk + 1][2], sc[2 * kk + 1][3]);
            uint32_t v4[4][4];
#pragma unroll
            for (int p = 0; p < 4; p++)
                ldsm4t(v4[p], vb + kk * (16 * ROWB) + p * 32);
#pragma unroll
            for (int nt = 0; nt < 8; nt++) {
                const int p = nt >> 1, o = (nt & 1) * 2;
                mma_f16(acc[nt], pf, v4[p][o], v4[p][o + 1]);
            }
        }
    }

    // ---- epilogue: ctx -> fp16 [B*T, C] ----
    const int b = bh / H_, h = bh - b * H_;
    const float i0 = 1.f / lsum[0];
    const float i1 = 1.f / lsum[1];
    const int r0 = q0 + m0 + (l >> 2);
    const size_t base0 = ((size_t)b * T_ + r0) * C_ + h * D_ + 2 * (l & 3);
    const size_t base1 = base0 + 8 * (size_t)C_;
#pragma unroll
    for (int nt = 0; nt < 8; nt++) {
        *(uint32_t*)&g_c[base0 + nt * 8] = pack_h2(acc[nt][0] * i0, acc[nt][1] * i0);
        *(uint32_t*)&g_c[base1 + nt * 8] = pack_h2(acc[nt][2] * i1, acc[nt][3] * i1);
    }
}

// ---------------------------------------------------------------------------
extern "C" void kernel_launch(void* const* d_in, const int* in_sizes, int n_in,
                              void* d_out, int out_size)
{
    const float* hidden = (const float*)d_in[0];
    const float* qkv_w  = (const float*)d_in[1];
    const float* qkv_b  = (const float*)d_in[2];
    const float* proj_w = (const float*)d_in[3];
    const float* proj_b = (const float*)d_in[4];
    float* out = (float*)d_out;
    (void)in_sizes; (void)n_in; (void)out_size;

    cudaFuncSetAttribute(gemm_mma_kernel<0>,
                         cudaFuncAttributeMaxDynamicSharedMemorySize, GEMM_SMEM);
    cudaFuncSetAttribute(gemm_mma_kernel<1>,
                         cudaFuncAttributeMaxDynamicSharedMemorySize, GEMM_SMEM);
    cudaFuncSetAttribute(attn_mma_kernel,
                         cudaFuncAttributeMaxDynamicSharedMemorySize, ATTN_SMEM);

    // 0) fused operand conversions (one launch)
    conv_all_kernel<<<NB_H + NB_WQ + NB_WP, 256>>>(hidden, qkv_w, proj_w);

    // 1) QKV projection -> Q (pre-scaled) / K / V fp16
    gemm_mma_kernel<0><<<dim3(N1_ / 128, M_ / 128), 256, GEMM_SMEM>>>(qkv_b, nullptr);

    // 2) attention -> ctx fp16
    attn_mma_kernel<<<dim3(T_ / 128, B_ * H_), 256, ATTN_SMEM>>>();

    // 3) output projection (128x128 CTAs) -> out fp32
    gemm_mma_kernel<1><<<dim3(C_ / 128, M_ / 128), 256, GEMM_SMEM>>>(proj_b, out);
}

// round 16
// speedup vs baseline: 1.0747x; 1.0342x over previous
#include <cuda_runtime.h>
#include <cuda_fp16.h>
#include <cstdint>
#include <cstddef>

#define B_   8
#define T_   1024
#define C_   768
#define H_   12
#define D_   64
#define M_   (B_ * T_)     /* 8192 */
#define N1_  (3 * C_)      /* 2304 */

// ---------------- device-global scratch (all fp16 single) -------------------
__device__ __half g_a [(size_t)M_ * C_];     // hidden
__device__ __half g_c [(size_t)M_ * C_];     // ctx
__device__ __half g_wq[(size_t)N1_ * C_];    // qkv_w^T [2304,768]
__device__ __half g_wp[(size_t)C_ * C_];     // proj_w^T [768,768]
__device__ __half g_q [(size_t)M_ * C_];     // [B*H,T,D], pre-scaled 0.125
__device__ __half g_k [(size_t)M_ * C_];
__device__ __half g_v [(size_t)M_ * C_];

// ---------------- PTX helpers ----------------------------------------------
__device__ __forceinline__ uint32_t smem_u32(const void* p) {
    uint32_t a;
    asm("{ .reg .u64 t; cvta.to.shared.u64 t, %1; cvt.u32.u64 %0, t; }"
        : "=r"(a) : "l"(p));
    return a;
}

#define CP_ASYNC16(dst, src) \
    asm volatile("cp.async.cg.shared.global [%0], [%1], 16;" \
                 :: "r"(dst), "l"(src) : "memory")
#define CP_COMMIT() asm volatile("cp.async.commit_group;" ::: "memory")
#define CP_WAIT(n)  asm volatile("cp.async.wait_group %0;" :: "n"(n) : "memory")

__device__ __forceinline__ void ldsm4(uint32_t* r, uint32_t a) {
    asm volatile("ldmatrix.sync.aligned.m8n8.x4.shared.b16 {%0,%1,%2,%3}, [%4];"
                 : "=r"(r[0]), "=r"(r[1]), "=r"(r[2]), "=r"(r[3]) : "r"(a));
}
__device__ __forceinline__ void ldsm4t(uint32_t* r, uint32_t a) {
    asm volatile("ldmatrix.sync.aligned.m8n8.x4.trans.shared.b16 {%0,%1,%2,%3}, [%4];"
                 : "=r"(r[0]), "=r"(r[1]), "=r"(r[2]), "=r"(r[3]) : "r"(a));
}

__device__ __forceinline__ void mma_f16(float* c, const uint32_t* a,
                                        uint32_t b0, uint32_t b1) {
    asm volatile(
        "mma.sync.aligned.m16n8k16.row.col.f32.f16.f16.f32 "
        "{%0,%1,%2,%3}, {%4,%5,%6,%7}, {%8,%9}, {%0,%1,%2,%3};"
        : "+f"(c[0]), "+f"(c[1]), "+f"(c[2]), "+f"(c[3])
        : "r"(a[0]), "r"(a[1]), "r"(a[2]), "r"(a[3]), "r"(b0), "r"(b1));
}

__device__ __forceinline__ uint32_t pack_h2(float x, float y) {
    __half2 h = __halves2half2(__float2half_rn(x), __float2half_rn(y));
    return *(uint32_t*)&h;
}

// ---------------- fused conversion kernel -----------------------------------
#define NB_H  ((M_ * C_) / 256)          /* 24576 */
#define NB_WQ ((N1_ / 32) * (C_ / 32))   /* 1728 */
#define NB_WP ((C_ / 32) * (C_ / 32))    /* 576 */

__global__ void conv_all_kernel(const float* __restrict__ hidden,
                                const float* __restrict__ qkv_w,
                                const float* __restrict__ proj_w)
{
    const int bid = blockIdx.x;
    const int tid = threadIdx.x;

    if (bid < NB_H) {
        int i = bid * 256 + tid;
        g_a[i] = __float2half_rn(hidden[i]);
        return;
    }

    __shared__ float tile[32][33];
    const float* src;
    __half* dst;
    int N, b;
    if (bid < NB_H + NB_WQ) {
        b = bid - NB_H;  src = qkv_w;  dst = g_wq;  N = N1_;
    } else {
        b = bid - NB_H - NB_WQ;  src = proj_w;  dst = g_wp;  N = C_;
    }
    const int nblk = N / 32;
    const int nx = (b % nblk) * 32;
    const int kx = (b / nblk) * 32;
    const int tx = tid & 31;
    const int ty = tid >> 5;
    for (int i = ty; i < 32; i += 8)
        tile[i][tx] = src[(size_t)(kx + i) * N + nx + tx];
    __syncthreads();
    for (int i = ty; i < 32; i += 8)
        dst[(size_t)(nx + i) * C_ + kx + tx] = __float2half_rn(tile[tx][i]);
}

// ---------------- mma.sync fp16 GEMM ----------------------------------------
// MODE 0: QKV. CTA 128x128, warp 32x64. grid 18x64 (1152 CTAs).
// MODE 1: proj. CTA 128x96, warp 32x48. grid 8x64 (512 CTAs, ~1.7 waves).
// BK = 64 elems (12 k-iters, half the barriers), 3-stage, 2 CTAs/SM.
#define BKE 64
#define KSB 144                       /* 64*2 + 16B pad; bank-quad clean */
#define TILE_A (128 * KSB)            /* 18432 */
#define NSTG 3
#define NKT 12

template <int MODE>
__global__ __launch_bounds__(256, 2)
void gemm_mma_kernel(const float* __restrict__ bias, float* __restrict__ out)
{
    constexpr int BN  = MODE ? 96 : 128;
    constexpr int WN  = BN / 2;                 // warp n-width (48 | 64)
    constexpr int NTW = WN / 8;                 // n-tiles per warp (6 | 8)
    constexpr int NP  = NTW / 2;                // b-ldsm4 per kk (3 | 4)
    constexpr uint32_t TILE_B_SZ = (uint32_t)BN * KSB;
    constexpr uint32_t STG_B = TILE_A + TILE_B_SZ;
    constexpr int NCHUNK = (128 + BN) * 8;      // 16B chunks per stage

    extern __shared__ char smem[];
    const uint32_t sbase = smem_u32(smem);
    const int tid = threadIdx.x;
    const int wid = tid >> 5;          // 0..7
    const int l   = tid & 31;
    const int gm0 = blockIdx.y * 128;
    const int gn0 = blockIdx.x * BN;

    const __half* gA = MODE ? g_c  : g_a;
    const __half* gB = MODE ? g_wp : g_wq;

    const int m0 = (wid & 3) * 32;
    const int n0 = (wid >> 2) * WN;

    const int lq = l >> 3, lr = l & 7;
    const uint32_t a_off = (uint32_t)((m0 + (lq & 1) * 8 + lr) * KSB + (lq >> 1) * 16);
    const uint32_t b_off = (uint32_t)((n0 + (lq >> 1) * 8 + lr) * KSB + (lq & 1) * 16);

    float acc[2][NTW][4];
#pragma unroll
    for (int mt = 0; mt < 2; mt++)
#pragma unroll
        for (int nt = 0; nt < NTW; nt++)
#pragma unroll
            for (int j = 0; j < 4; j++) acc[mt][nt][j] = 0.f;

    auto issue_stage = [&](int kt, int s) {
        const int k0 = kt * BKE;
        const uint32_t sb = sbase + (uint32_t)s * STG_B;
#pragma unroll
        for (int c = tid; c < NCHUNK; c += 256) {
            const int row = c >> 3, ch = c & 7;
            const __half* src = (row < 128) ? gA : gB;
            const int grow = (row < 128) ? (gm0 + row) : (gn0 + row - 128);
            CP_ASYNC16(sb + (uint32_t)row * KSB + ch * 16,
                       src + (size_t)grow * C_ + k0 + ch * 8);
        }
    };

    issue_stage(0, 0); CP_COMMIT();
    issue_stage(1, 1); CP_COMMIT();

#pragma unroll 1
    for (int kt = 0; kt < NKT; kt++) {
        const int s = kt % NSTG;
        if (kt + 1 < NKT) { CP_WAIT(1); } else { CP_WAIT(0); }
        __syncthreads();
        if (kt + 2 < NKT) {
            issue_stage(kt + 2, (kt + 2) % NSTG);
            CP_COMMIT();
        }

        const uint32_t aP = sbase + (uint32_t)s * STG_B + a_off;
        const uint32_t bP = sbase + (uint32_t)s * STG_B + TILE_A + b_off;

#pragma unroll
        for (int kk = 0; kk < 4; kk++) {
            const uint32_t ko = kk * 32;
            uint32_t ar[2][4], br[NP][4];
#pragma unroll
            for (int mt = 0; mt < 2; mt++)
                ldsm4(ar[mt], aP + mt * (16 * KSB) + ko);
#pragma unroll
            for (int p = 0; p < NP; p++)
                ldsm4(br[p], bP + p * (16 * KSB) + ko);
#pragma unroll
            for (int mt = 0; mt < 2; mt++)
#pragma unroll
                for (int nt = 0; nt < NTW; nt++) {
                    const int p = nt >> 1, o = (nt & 1) * 2;
                    mma_f16(acc[mt][nt], ar[mt], br[p][o], br[p][o + 1]);
                }
        }
    }

    // ---------------- epilogue ----------------------------------------------
    const int gr_base = gm0 + m0 + (l >> 2);
    const int gc_loc  = 2 * (l & 3);

    if (MODE == 0) {
        const int which    = gn0 / C_;
        const int rem_base = gn0 - which * C_;
        __half* dst = (which == 0) ? g_q : (which == 1) ? g_k : g_v;
        const float sc = (which == 0) ? 0.125f : 1.0f;
#pragma unroll
        for (int mt = 0; mt < 2; mt++)
#pragma unroll
            for (int nt = 0; nt < NTW; nt++) {
                const float* c = acc[mt][nt];
                const int gcn = n0 + nt * 8 + gc_loc;
                const int gc  = gn0 + gcn;
                float2 bb = *(const float2*)&bias[gc];
                const int rem = rem_base + gcn;
                const int h = rem >> 6, d = rem & 63;
#pragma unroll
                for (int hf = 0; hf < 2; hf++) {
                    const int gr = gr_base + mt * 16 + hf * 8;
                    const int b  = gr >> 10, tq = gr & 1023;
                    size_t idx = (((size_t)(b * H_ + h)) * T_ + tq) * D_ + d;
                    *(uint32_t*)&dst[idx] = pack_h2((c[hf * 2 + 0] + bb.x) * sc,
                                                    (c[hf * 2 + 1] + bb.y) * sc);
                }
            }
    } else {
#pragma unroll
        for (int mt = 0; mt < 2; mt++)
#pragma unroll
            for (int nt = 0; nt < NTW; nt++) {
                const float* c = acc[mt][nt];
                const int gc = gn0 + n0 + nt * 8 + gc_loc;
                float2 bb = *(const float2*)&bias[gc];
#pragma unroll
                for (int hf = 0; hf < 2; hf++) {
                    const int gr = gr_base + mt * 16 + hf * 8;
                    float2 o;
                    o.x = c[hf * 2 + 0] + bb.x;
                    o.y = c[hf * 2 + 1] + bb.y;
                    *(float2*)&out[(size_t)gr * C_ + gc] = o;
                }
            }
    }
}

#define GEMM_SMEM0 (NSTG * (TILE_A + 128 * KSB))  /* 110592 */
#define GEMM_SMEM1 (NSTG * (TILE_A + 96 * KSB))   /* 96768 */

// ---------------- tensor-core flash attention (fp16, register P) ------------
// CTA: 128 q-rows x (b,h). 8 warps x 16 rows. 64-key tiles, 16 iters.
// 3-stage KV ring, ONE barrier per iteration; P stays in registers.
#define NT_  16
#define ROWB 144
#define SQ    0                               /* 18432 */
#define SK(s) (18432 + (s) * 18432)           /* K tile (9216) */
#define SV(s) (18432 + (s) * 18432 + 9216)    /* V tile (9216) */
#define ATTN_SMEM (18432 * 4)                 /* 73728 */

__global__ __launch_bounds__(256, 2) void attn_mma_kernel()
{
    extern __shared__ char smem[];
    const uint32_t sbase = smem_u32(smem);
    const int tid = threadIdx.x, wid = tid >> 5, l = tid & 31;
    const int bh = blockIdx.y, q0 = blockIdx.x * 128;
    const size_t hb = (size_t)bh * T_ * D_;
    const __half *Qg = g_q + hb, *Kg = g_k + hb, *Vg = g_v + hb;

    const int m0 = wid * 16;
    const int lq = l >> 3, lr = l & 7;
    const uint32_t a_off = (uint32_t)((m0 + (lq & 1) * 8 + lr) * ROWB + (lq >> 1) * 16);
    const uint32_t b_off = (uint32_t)(((lq >> 1) * 8 + lr) * ROWB + (lq & 1) * 16);
    const uint32_t v_off = (uint32_t)(((lq & 1) * 8 + lr) * ROWB + (lq >> 1) * 16);

    auto load_kv = [&](int kt, int s) {
        const int r0 = kt * 64;
#pragma unroll
        for (int a = 0; a < 2; a++) {
            const __half* src = a ? Vg : Kg;
            const uint32_t dst = sbase + (a ? SV(s) : SK(s));
#pragma unroll
            for (int it = 0; it < 2; it++) {
                int c = it * 256 + tid;
                int row = c >> 3, ch = c & 7;
                CP_ASYNC16(dst + row * ROWB + ch * 16,
                           src + (size_t)(r0 + row) * D_ + ch * 8);
            }
        }
    };

#pragma unroll
    for (int it = 0; it < 4; it++) {
        int c = it * 256 + tid;
        int row = c >> 3, ch = c & 7;
        CP_ASYNC16(sbase + SQ + row * ROWB + ch * 16,
                   Qg + (size_t)(q0 + row) * D_ + ch * 8);
    }
    load_kv(0, 0); CP_COMMIT();
    load_kv(1, 1); CP_COMMIT();

    uint32_t qf[4][4];
    float mrow[2] = {-1e30f, -1e30f}, lsum[2] = {0.f, 0.f};
    float acc[8][4];
#pragma unroll
    for (int nt = 0; nt < 8; nt++)
#pragma unroll
        for (int j = 0; j < 4; j++) acc[nt][j] = 0.f;

#pragma unroll 1
    for (int kt = 0; kt < NT_; kt++) {
        const int s = kt % 3;
        if (kt + 1 < NT_) { CP_WAIT(1); } else { CP_WAIT(0); }
        __syncthreads();
        if (kt == 0) {
#pragma unroll
            for (int kk = 0; kk < 4; kk++)
                ldsm4(qf[kk], sbase + SQ + a_off + kk * 32);
        }
        if (kt + 2 < NT_) {
            load_kv(kt + 2, (kt + 2) % 3);
            CP_COMMIT();
        }

        // ---- S = Q K^T ----
        float sc[8][4];
#pragma unroll
        for (int nt = 0; nt < 8; nt++)
#pragma unroll
            for (int j = 0; j < 4; j++) sc[nt][j] = 0.f;

        const uint32_t kb = sbase + SK(s) + b_off;
#pragma unroll
        for (int kk = 0; kk < 4; kk++) {
            uint32_t b4[4][4];
#pragma unroll
            for (int p = 0; p < 4; p++)
                ldsm4(b4[p], kb + p * (16 * ROWB) + kk * 32);
#pragma unroll
            for (int nt = 0; nt < 8; nt++) {
                const int p = nt >> 1, o = (nt & 1) * 2;
                mma_f16(sc[nt], qf[kk], b4[p][o], b4[p][o + 1]);
            }
        }

        // ---- online softmax (p kept in sc registers) ----
        float mx0 = sc[0][0], mx1 = sc[0][2];
#pragma unroll
        for (int nt = 0; nt < 8; nt++) {
            mx0 = fmaxf(mx0, fmaxf(sc[nt][0], sc[nt][1]));
            mx1 = fmaxf(mx1, fmaxf(sc[nt][2], sc[nt][3]));
        }
        mx0 = fmaxf(mx0, __shfl_xor_sync(0xffffffffu, mx0, 1));
        mx0 = fmaxf(mx0, __shfl_xor_sync(0xffffffffu, mx0, 2));
        mx1 = fmaxf(mx1, __shfl_xor_sync(0xffffffffu, mx1, 1));
        mx1 = fmaxf(mx1, __shfl_xor_sync(0xffffffffu, mx1, 2));
        const float mn0 = fmaxf(mrow[0], mx0);
        const float mn1 = fmaxf(mrow[1], mx1);
        const float f0 = __expf(mrow[0] - mn0);
        const float f1 = __expf(mrow[1] - mn1);
        mrow[0] = mn0; mrow[1] = mn1;

        float rs0 = 0.f, rs1 = 0.f;
#pragma unroll
        for (int nt = 0; nt < 8; nt++) {
            float p0 = __expf(sc[nt][0] - mn0);
            float p1 = __expf(sc[nt][1] - mn0);
            float p2 = __expf(sc[nt][2] - mn1);
            float p3 = __expf(sc[nt][3] - mn1);
            rs0 += p0 + p1; rs1 += p2 + p3;
            sc[nt][0] = p0; sc[nt][1] = p1; sc[nt][2] = p2; sc[nt][3] = p3;
            acc[nt][0] *= f0; acc[nt][1] *= f0;
            acc[nt][2] *= f1; acc[nt][3] *= f1;
        }
        rs0 += __shfl_xor_sync(0xffffffffu, rs0, 1);
        rs0 += __shfl_xor_sync(0xffffffffu, rs0, 2);
        rs1 += __shfl_xor_sync(0xffffffffu, rs1, 1);
        rs1 += __shfl_xor_sync(0xffffffffu, rs1, 2);
        lsum[0] = lsum[0] * f0 + rs0;
        lsum[1] = lsum[1] * f1 + rs1;

        // ---- O += P V, P fragments built in registers ----
        const uint32_t vb = sbase + SV(s) + v_off;
#pragma unroll
        for (int kk = 0; kk < 4; kk++) {
            uint32_t pf[4];
            pf[0] = pack_h2(sc[2 * kk][0],     sc[2 * kk][1]);
            pf[1] = pack_h2(sc[2 * kk][2],     sc[2 * kk][3]);
            pf[2] = pack_h2(sc[2 * kk + 1][0], sc[2 * kk + 1][1]);
            pf[3] = pack_h2(sc[2 * kk + 1][2], sc[2 * kk + 1][3]);
            uint32_t v4[4][4];
#pragma unroll
            for (int p = 0; p < 4; p++)
                ldsm4t(v4[p], vb + kk * (16 * ROWB) + p * 32);
#pragma unroll
            for (int nt = 0; nt < 8; nt++) {
                const int p = nt >> 1, o = (nt & 1) * 2;
                mma_f16(acc[nt], pf, v4[p][o], v4[p][o + 1]);
            }
        }
    }

    // ---- epilogue: ctx -> fp16 [B*T, C] ----
    const int b = bh / H_, h = bh - b * H_;
    const float i0 = 1.f / lsum[0];
    const float i1 = 1.f / lsum[1];
    const int r0 = q0 + m0 + (l >> 2);
    const size_t base0 = ((size_t)b * T_ + r0) * C_ + h * D_ + 2 * (l & 3);
    const size_t base1 = base0 + 8 * (size_t)C_;
#pragma unroll
    for (int nt = 0; nt < 8; nt++) {
        *(uint32_t*)&g_c[base0 + nt * 8] = pack_h2(acc[nt][0] * i0, acc[nt][1] * i0);
        *(uint32_t*)&g_c[base1 + nt * 8] = pack_h2(acc[nt][2] * i1, acc[nt][3] * i1);
    }
}

// ---------------------------------------------------------------------------
extern "C" void kernel_launch(void* const* d_in, const int* in_sizes, int n_in,
                              void* d_out, int out_size)
{
    const float* hidden = (const float*)d_in[0];
    const float* qkv_w  = (const float*)d_in[1];
    const float* qkv_b  = (const float*)d_in[2];
    const float* proj_w = (const float*)d_in[3];
    const float* proj_b = (const float*)d_in[4];
    float* out = (float*)d_out;
    (void)in_sizes; (void)n_in; (void)out_size;

    cudaFuncSetAttribute(gemm_mma_kernel<0>,
                         cudaFuncAttributeMaxDynamicSharedMemorySize, GEMM_SMEM0);
    cudaFuncSetAttribute(gemm_mma_kernel<1>,
                         cudaFuncAttributeMaxDynamicSharedMemorySize, GEMM_SMEM1);
    cudaFuncSetAttribute(attn_mma_kernel,
                         cudaFuncAttributeMaxDynamicSharedMemorySize, ATTN_SMEM);

    // 0) fused operand conversions (one launch)
    conv_all_kernel<<<NB_H + NB_WQ + NB_WP, 256>>>(hidden, qkv_w, proj_w);

    // 1) QKV projection -> Q (pre-scaled) / K / V fp16
    gemm_mma_kernel<0><<<dim3(N1_ / 128, M_ / 128), 256, GEMM_SMEM0>>>(qkv_b, nullptr);

    // 2) attention -> ctx fp16
    attn_mma_kernel<<<dim3(T_ / 128, B_ * H_), 256, ATTN_SMEM>>>();

    // 3) output projection (128x96 CTAs, 512 CTAs) -> out fp32
    gemm_mma_kernel<1><<<dim3(C_ / 96, M_ / 128), 256, GEMM_SMEM1>>>(proj_b, out);
}

// round 17
// speedup vs baseline: 1.1357x; 1.0567x over previous
#include <cuda_runtime.h>
#include <cuda_fp16.h>
#include <cstdint>
#include <cstddef>

#define B_   8
#define T_   1024
#define C_   768
#define H_   12
#define D_   64
#define M_   (B_ * T_)     /* 8192 */
#define N1_  (3 * C_)      /* 2304 */

// ---------------- device-global scratch (all fp16 single) -------------------
__device__ __half g_a [(size_t)M_ * C_];     // hidden
__device__ __half g_c [(size_t)M_ * C_];     // ctx
__device__ __half g_wq[(size_t)N1_ * C_];    // qkv_w^T [2304,768]
__device__ __half g_wp[(size_t)C_ * C_];     // proj_w^T [768,768]
__device__ __half g_q [(size_t)M_ * C_];     // [B*H,T,D], pre-scaled 0.125
__device__ __half g_k [(size_t)M_ * C_];
__device__ __half g_v [(size_t)M_ * C_];

// ---------------- PTX helpers ----------------------------------------------
__device__ __forceinline__ uint32_t smem_u32(const void* p) {
    uint32_t a;
    asm("{ .reg .u64 t; cvta.to.shared.u64 t, %1; cvt.u32.u64 %0, t; }"
        : "=r"(a) : "l"(p));
    return a;
}

#define CP_ASYNC16(dst, src) \
    asm volatile("cp.async.cg.shared.global [%0], [%1], 16;" \
                 :: "r"(dst), "l"(src) : "memory")
#define CP_COMMIT() asm volatile("cp.async.commit_group;" ::: "memory")
#define CP_WAIT(n)  asm volatile("cp.async.wait_group %0;" :: "n"(n) : "memory")

__device__ __forceinline__ void ldsm4(uint32_t* r, uint32_t a) {
    asm volatile("ldmatrix.sync.aligned.m8n8.x4.shared.b16 {%0,%1,%2,%3}, [%4];"
                 : "=r"(r[0]), "=r"(r[1]), "=r"(r[2]), "=r"(r[3]) : "r"(a));
}
__device__ __forceinline__ void ldsm4t(uint32_t* r, uint32_t a) {
    asm volatile("ldmatrix.sync.aligned.m8n8.x4.trans.shared.b16 {%0,%1,%2,%3}, [%4];"
                 : "=r"(r[0]), "=r"(r[1]), "=r"(r[2]), "=r"(r[3]) : "r"(a));
}

__device__ __forceinline__ void mma_f16(float* c, const uint32_t* a,
                                        uint32_t b0, uint32_t b1) {
    asm volatile(
        "mma.sync.aligned.m16n8k16.row.col.f32.f16.f16.f32 "
        "{%0,%1,%2,%3}, {%4,%5,%6,%7}, {%8,%9}, {%0,%1,%2,%3};"
        : "+f"(c[0]), "+f"(c[1]), "+f"(c[2]), "+f"(c[3])
        : "r"(a[0]), "r"(a[1]), "r"(a[2]), "r"(a[3]), "r"(b0), "r"(b1));
}

__device__ __forceinline__ uint32_t pack_h2(float x, float y) {
    __half2 h = __halves2half2(__float2half_rn(x), __float2half_rn(y));
    return *(uint32_t*)&h;
}

// ---------------- fused conversion kernel -----------------------------------
// hidden path: 8 floats/thread (2x float4 -> uint4 of 4 half2), DRAM-bound.
#define NB_H  ((M_ * C_) / 2048)         /* 3072 */
#define NB_WQ ((N1_ / 32) * (C_ / 32))   /* 1728 */
#define NB_WP ((C_ / 32) * (C_ / 32))    /* 576 */

__global__ void conv_all_kernel(const float* __restrict__ hidden,
                                const float* __restrict__ qkv_w,
                                const float* __restrict__ proj_w)
{
    const int bid = blockIdx.x;
    const int tid = threadIdx.x;

    if (bid < NB_H) {
        const size_t i = (size_t)bid * 2048 + (size_t)tid * 8;
        float4 v0 = *(const float4*)(hidden + i);
        float4 v1 = *(const float4*)(hidden + i + 4);
        uint4 o;
        o.x = pack_h2(v0.x, v0.y);
        o.y = pack_h2(v0.z, v0.w);
        o.z = pack_h2(v1.x, v1.y);
        o.w = pack_h2(v1.z, v1.w);
        *(uint4*)(g_a + i) = o;
        return;
    }

    __shared__ float tile[32][33];
    const float* src;
    __half* dst;
    int N, b;
    if (bid < NB_H + NB_WQ) {
        b = bid - NB_H;  src = qkv_w;  dst = g_wq;  N = N1_;
    } else {
        b = bid - NB_H - NB_WQ;  src = proj_w;  dst = g_wp;  N = C_;
    }
    const int nblk = N / 32;
    const int nx = (b % nblk) * 32;
    const int kx = (b / nblk) * 32;
    const int tx = tid & 31;
    const int ty = tid >> 5;
    for (int i = ty; i < 32; i += 8)
        tile[i][tx] = src[(size_t)(kx + i) * N + nx + tx];
    __syncthreads();
    for (int i = ty; i < 32; i += 8)
        dst[(size_t)(nx + i) * C_ + kx + tx] = __float2half_rn(tile[tx][i]);
}

// ---------------- mma.sync fp16 GEMM ----------------------------------------
// MODE 0: QKV. CTA 128x128, warp 32x64. grid 18x64 (1152 CTAs).
// MODE 1: proj. CTA 128x96, warp 32x48. grid 8x64 (512 CTAs).
// BK = 64 elems (12 k-iters), 3-stage, 2 CTAs/SM.
#define BKE 64
#define KSB 144                       /* 64*2 + 16B pad; bank-quad clean */
#define TILE_A (128 * KSB)            /* 18432 */
#define NSTG 3
#define NKT 12

template <int MODE>
__global__ __launch_bounds__(256, 2)
void gemm_mma_kernel(const float* __restrict__ bias, float* __restrict__ out)
{
    constexpr int BN  = MODE ? 96 : 128;
    constexpr int WN  = BN / 2;                 // warp n-width (48 | 64)
    constexpr int NTW = WN / 8;                 // n-tiles per warp (6 | 8)
    constexpr int NP  = NTW / 2;                // b-ldsm4 per kk (3 | 4)
    constexpr uint32_t TILE_B_SZ = (uint32_t)BN * KSB;
    constexpr uint32_t STG_B = TILE_A + TILE_B_SZ;
    constexpr int NCHUNK = (128 + BN) * 8;      // 16B chunks per stage

    extern __shared__ char smem[];
    const uint32_t sbase = smem_u32(smem);
    const int tid = threadIdx.x;
    const int wid = tid >> 5;          // 0..7
    const int l   = tid & 31;
    const int gm0 = blockIdx.y * 128;
    const int gn0 = blockIdx.x * BN;

    const __half* gA = MODE ? g_c  : g_a;
    const __half* gB = MODE ? g_wp : g_wq;

    const int m0 = (wid & 3) * 32;
    const int n0 = (wid >> 2) * WN;

    const int lq = l >> 3, lr = l & 7;
    const uint32_t a_off = (uint32_t)((m0 + (lq & 1) * 8 + lr) * KSB + (lq >> 1) * 16);
    const uint32_t b_off = (uint32_t)((n0 + (lq >> 1) * 8 + lr) * KSB + (lq & 1) * 16);

    float acc[2][NTW][4];
#pragma unroll
    for (int mt = 0; mt < 2; mt++)
#pragma unroll
        for (int nt = 0; nt < NTW; nt++)
#pragma unroll
            for (int j = 0; j < 4; j++) acc[mt][nt][j] = 0.f;

    auto issue_stage = [&](int kt, int s) {
        const int k0 = kt * BKE;
        const uint32_t sb = sbase + (uint32_t)s * STG_B;
#pragma unroll
        for (int c = tid; c < NCHUNK; c += 256) {
            const int row = c >> 3, ch = c & 7;
            const __half* src = (row < 128) ? gA : gB;
            const int grow = (row < 128) ? (gm0 + row) : (gn0 + row - 128);
            CP_ASYNC16(sb + (uint32_t)row * KSB + ch * 16,
                       src + (size_t)grow * C_ + k0 + ch * 8);
        }
    };

    issue_stage(0, 0); CP_COMMIT();
    issue_stage(1, 1); CP_COMMIT();

#pragma unroll 1
    for (int kt = 0; kt < NKT; kt++) {
        const int s = kt % NSTG;
        if (kt + 1 < NKT) { CP_WAIT(1); } else { CP_WAIT(0); }
        __syncthreads();
        if (kt + 2 < NKT) {
            issue_stage(kt + 2, (kt + 2) % NSTG);
            CP_COMMIT();
        }

        const uint32_t aP = sbase + (uint32_t)s * STG_B + a_off;
        const uint32_t bP = sbase + (uint32_t)s * STG_B + TILE_A + b_off;

#pragma unroll
        for (int kk = 0; kk < 4; kk++) {
            const uint32_t ko = kk * 32;
            uint32_t ar[2][4], br[NP][4];
#pragma unroll
            for (int mt = 0; mt < 2; mt++)
                ldsm4(ar[mt], aP + mt * (16 * KSB) + ko);
#pragma unroll
            for (int p = 0; p < NP; p++)
                ldsm4(br[p], bP + p * (16 * KSB) + ko);
#pragma unroll
            for (int mt = 0; mt < 2; mt++)
#pragma unroll
                for (int nt = 0; nt < NTW; nt++) {
                    const int p = nt >> 1, o = (nt & 1) * 2;
                    mma_f16(acc[mt][nt], ar[mt], br[p][o], br[p][o + 1]);
                }
        }
    }

    // ---------------- epilogue ----------------------------------------------
    const int gr_base = gm0 + m0 + (l >> 2);
    const int gc_loc  = 2 * (l & 3);

    if (MODE == 0) {
        const int which    = gn0 / C_;
        const int rem_base = gn0 - which * C_;
        __half* dst = (which == 0) ? g_q : (which == 1) ? g_k : g_v;
        const float sc = (which == 0) ? 0.125f : 1.0f;
#pragma unroll
        for (int mt = 0; mt < 2; mt++)
#pragma unroll
            for (int nt = 0; nt < NTW; nt++) {
                const float* c = acc[mt][nt];
                const int gcn = n0 + nt * 8 + gc_loc;
                const int gc  = gn0 + gcn;
                float2 bb = *(const float2*)&bias[gc];
                const int rem = rem_base + gcn;
                const int h = rem >> 6, d = rem & 63;
#pragma unroll
                for (int hf = 0; hf < 2; hf++) {
                    const int gr = gr_base + mt * 16 + hf * 8;
                    const int b  = gr >> 10, tq = gr & 1023;
                    size_t idx = (((size_t)(b * H_ + h)) * T_ + tq) * D_ + d;
                    *(uint32_t*)&dst[idx] = pack_h2((c[hf * 2 + 0] + bb.x) * sc,
                                                    (c[hf * 2 + 1] + bb.y) * sc);
                }
            }
    } else {
#pragma unroll
        for (int mt = 0; mt < 2; mt++)
#pragma unroll
            for (int nt = 0; nt < NTW; nt++) {
                const float* c = acc[mt][nt];
                const int gc = gn0 + n0 + nt * 8 + gc_loc;
                float2 bb = *(const float2*)&bias[gc];
#pragma unroll
                for (int hf = 0; hf < 2; hf++) {
                    const int gr = gr_base + mt * 16 + hf * 8;
                    float2 o;
                    o.x = c[hf * 2 + 0] + bb.x;
                    o.y = c[hf * 2 + 1] + bb.y;
                    *(float2*)&out[(size_t)gr * C_ + gc] = o;
                }
            }
    }
}

#define GEMM_SMEM0 (NSTG * (TILE_A + 128 * KSB))  /* 110592 */
#define GEMM_SMEM1 (NSTG * (TILE_A + 96 * KSB))   /* 96768 */

// ---------------- tensor-core flash attention (fp16, register P) ------------
// CTA: 128 q-rows x (b,h). 8 warps x 16 rows. 64-key tiles, 16 iters.
// 3-stage KV ring, ONE barrier per iteration; P stays in registers.
#define NT_  16
#define ROWB 144
#define SQ    0                               /* 18432 */
#define SK(s) (18432 + (s) * 18432)           /* K tile (9216) */
#define SV(s) (18432 + (s) * 18432 + 9216)    /* V tile (9216) */
#define ATTN_SMEM (18432 * 4)                 /* 73728 */

__global__ __launch_bounds__(256, 2) void attn_mma_kernel()
{
    extern __shared__ char smem[];
    const uint32_t sbase = smem_u32(smem);
    const int tid = threadIdx.x, wid = tid >> 5, l = tid & 31;
    const int bh = blockIdx.y, q0 = blockIdx.x * 128;
    const size_t hb = (size_t)bh * T_ * D_;
    const __half *Qg = g_q + hb, *Kg = g_k + hb, *Vg = g_v + hb;

    const int m0 = wid * 16;
    const int lq = l >> 3, lr = l & 7;
    const uint32_t a_off = (uint32_t)((m0 + (lq & 1) * 8 + lr) * ROWB + (lq >> 1) * 16);
    const uint32_t b_off = (uint32_t)(((lq >> 1) * 8 + lr) * ROWB + (lq & 1) * 16);
    const uint32_t v_off = (uint32_t)(((lq & 1) * 8 + lr) * ROWB + (lq >> 1) * 16);

    auto load_kv = [&](int kt, int s) {
        const int r0 = kt * 64;
#pragma unroll
        for (int a = 0; a < 2; a++) {
            const __half* src = a ? Vg : Kg;
            const uint32_t dst = sbase + (a ? SV(s) : SK(s));
#pragma unroll
            for (int it = 0; it < 2; it++) {
                int c = it * 256 + tid;
                int row = c >> 3, ch = c & 7;
                CP_ASYNC16(dst + row * ROWB + ch * 16,
                           src + (size_t)(r0 + row) * D_ + ch * 8);
            }
        }
    };

#pragma unroll
    for (int it = 0; it < 4; it++) {
        int c = it * 256 + tid;
        int row = c >> 3, ch = c & 7;
        CP_ASYNC16(sbase + SQ + row * ROWB + ch * 16,
                   Qg + (size_t)(q0 + row) * D_ + ch * 8);
    }
    load_kv(0, 0); CP_COMMIT();
    load_kv(1, 1); CP_COMMIT();

    uint32_t qf[4][4];
    float mrow[2] = {-1e30f, -1e30f}, lsum[2] = {0.f, 0.f};
    float acc[8][4];
#pragma unroll
    for (int nt = 0; nt < 8; nt++)
#pragma unroll
        for (int j = 0; j < 4; j++) acc[nt][j] = 0.f;

#pragma unroll 1
    for (int kt = 0; kt < NT_; kt++) {
        const int s = kt % 3;
        if (kt + 1 < NT_) { CP_WAIT(1); } else { CP_WAIT(0); }
        __syncthreads();
        if (kt == 0) {
#pragma unroll
            for (int kk = 0; kk < 4; kk++)
                ldsm4(qf[kk], sbase + SQ + a_off + kk * 32);
        }
        if (kt + 2 < NT_) {
            load_kv(kt + 2, (kt + 2) % 3);
            CP_COMMIT();
        }

        // ---- S = Q K^T ----
        float sc[8][4];
#pragma unroll
        for (int nt = 0; nt < 8; nt++)
#pragma unroll
            for (int j = 0; j < 4; j++) sc[nt][j] = 0.f;

        const uint32_t kb = sbase + SK(s) + b_off;
#pragma unroll
        for (int kk = 0; kk < 4; kk++) {
            uint32_t b4[4][4];
#pragma unroll
            for (int p = 0; p < 4; p++)
                ldsm4(b4[p], kb + p * (16 * ROWB) + kk * 32);
#pragma unroll
            for (int nt = 0; nt < 8; nt++) {
                const int p = nt >> 1, o = (nt & 1) * 2;
                mma_f16(sc[nt], qf[kk], b4[p][o], b4[p][o + 1]);
            }
        }

        // ---- online softmax (p kept in sc registers) ----
        float mx0 = sc[0][0], mx1 = sc[0][2];
#pragma unroll
        for (int nt = 0; nt < 8; nt++) {
            mx0 = fmaxf(mx0, fmaxf(sc[nt][0], sc[nt][1]));
            mx1 = fmaxf(mx1, fmaxf(sc[nt][2], sc[nt][3]));
        }
        mx0 = fmaxf(mx0, __shfl_xor_sync(0xffffffffu, mx0, 1));
        mx0 = fmaxf(mx0, __shfl_xor_sync(0xffffffffu, mx0, 2));
        mx1 = fmaxf(mx1, __shfl_xor_sync(0xffffffffu, mx1, 1));
        mx1 = fmaxf(mx1, __shfl_xor_sync(0xffffffffu, mx1, 2));
        const float mn0 = fmaxf(mrow[0], mx0);
        const float mn1 = fmaxf(mrow[1], mx1);
        const float f0 = __expf(mrow[0] - mn0);
        const float f1 = __expf(mrow[1] - mn1);
        mrow[0] = mn0; mrow[1] = mn1;

        float rs0 = 0.f, rs1 = 0.f;
#pragma unroll
        for (int nt = 0; nt < 8; nt++) {
            float p0 = __expf(sc[nt][0] - mn0);
            float p1 = __expf(sc[nt][1] - mn0);
            float p2 = __expf(sc[nt][2] - mn1);
            float p3 = __expf(sc[nt][3] - mn1);
            rs0 += p0 + p1; rs1 += p2 + p3;
            sc[nt][0] = p0; sc[nt][1] = p1; sc[nt][2] = p2; sc[nt][3] = p3;
            acc[nt][0] *= f0; acc[nt][1] *= f0;
            acc[nt][2] *= f1; acc[nt][3] *= f1;
        }
        rs0 += __shfl_xor_sync(0xffffffffu, rs0, 1);
        rs0 += __shfl_xor_sync(0xffffffffu, rs0, 2);
        rs1 += __shfl_xor_sync(0xffffffffu, rs1, 1);
        rs1 += __shfl_xor_sync(0xffffffffu, rs1, 2);
        lsum[0] = lsum[0] * f0 + rs0;
        lsum[1] = lsum[1] * f1 + rs1;

        // ---- O += P V, P fragments built in registers ----
        const uint32_t vb = sbase + SV(s) + v_off;
#pragma unroll
        for (int kk = 0; kk < 4; kk++) {
            uint32_t pf[4];
            pf[0] = pack_h2(sc[2 * kk][0],     sc[2 * kk][1]);
            pf[1] = pack_h2(sc[2 * kk][2],     sc[2 * kk][3]);
            pf[2] = pack_h2(sc[2 * kk + 1][0], sc[2 * kk + 1][1]);
            pf[3] = pack_h2(sc[2 * kk + 1][2], sc[2 * kk + 1][3]);
            uint32_t v4[4][4];
#pragma unroll
            for (int p = 0; p < 4; p++)
                ldsm4t(v4[p], vb + kk * (16 * ROWB) + p * 32);
#pragma unroll
            for (int nt = 0; nt < 8; nt++) {
                const int p = nt >> 1, o = (nt & 1) * 2;
                mma_f16(acc[nt], pf, v4[p][o], v4[p][o + 1]);
            }
        }
    }

    // ---- epilogue: ctx -> fp16 [B*T, C] ----
    const int b = bh / H_, h = bh - b * H_;
    const float i0 = 1.f / lsum[0];
    const float i1 = 1.f / lsum[1];
    const int r0 = q0 + m0 + (l >> 2);
    const size_t base0 = ((size_t)b * T_ + r0) * C_ + h * D_ + 2 * (l & 3);
    const size_t base1 = base0 + 8 * (size_t)C_;
#pragma unroll
    for (int nt = 0; nt < 8; nt++) {
        *(uint32_t*)&g_c[base0 + nt * 8] = pack_h2(acc[nt][0] * i0, acc[nt][1] * i0);
        *(uint32_t*)&g_c[base1 + nt * 8] = pack_h2(acc[nt][2] * i1, acc[nt][3] * i1);
    }
}

// ---------------------------------------------------------------------------
extern "C" void kernel_launch(void* const* d_in, const int* in_sizes, int n_in,
                              void* d_out, int out_size)
{
    const float* hidden = (const float*)d_in[0];
    const float* qkv_w  = (const float*)d_in[1];
    const float* qkv_b  = (const float*)d_in[2];
    const float* proj_w = (const float*)d_in[3];
    const float* proj_b = (const float*)d_in[4];
    float* out = (float*)d_out;
    (void)in_sizes; (void)n_in; (void)out_size;

    cudaFuncSetAttribute(gemm_mma_kernel<0>,
                         cudaFuncAttributeMaxDynamicSharedMemorySize, GEMM_SMEM0);
    cudaFuncSetAttribute(gemm_mma_kernel<1>,
                         cudaFuncAttributeMaxDynamicSharedMemorySize, GEMM_SMEM1);
    cudaFuncSetAttribute(attn_mma_kernel,
                         cudaFuncAttributeMaxDynamicSharedMemorySize, ATTN_SMEM);

    // 0) fused operand conversions (one launch, vectorized hidden path)
    conv_all_kernel<<<NB_H + NB_WQ + NB_WP, 256>>>(hidden, qkv_w, proj_w);

    // 1) QKV projection -> Q (pre-scaled) / K / V fp16
    gemm_mma_kernel<0><<<dim3(N1_ / 128, M_ / 128), 256, GEMM_SMEM0>>>(qkv_b, nullptr);

    // 2) attention -> ctx fp16
    attn_mma_kernel<<<dim3(T_ / 128, B_ * H_), 256, ATTN_SMEM>>>();

    // 3) output projection (128x96 CTAs) -> out fp32
    gemm_mma_kernel<1><<<dim3(C_ / 96, M_ / 128), 256, GEMM_SMEM1>>>(proj_b, out);
}